// round 2
// baseline (speedup 1.0000x reference)
#include <cuda_runtime.h>
#include <cstdint>

#define S_LEN 512
#define B_SZ  64
#define HIDD  1024
#define EMBD  512
#define NCLS  32000
#define FEATD 2048
#define RNN_NCTA 128
#define RNN_SMEM ((32 * 260 + 64 * 260) * 4)

// ---- device scratch (statics: no allocation allowed) ----
__device__ float g_G[(size_t)S_LEN * B_SZ * HIDD];
__device__ float g_OUT[(size_t)S_LEN * B_SZ * HIDD];
__device__ float g_P[4 * B_SZ * HIDD];
__device__ float g_h0[B_SZ * HIDD];
__device__ float g_scores[(S_LEN - 1) * B_SZ];
__device__ float g_attn[(S_LEN - 1) * B_SZ];
__device__ float g_attout[B_SZ * HIDD];
__device__ unsigned g_bar_cnt;
__device__ volatile unsigned g_bar_gen;

__global__ void init_kernel() {
    int i = blockIdx.x * blockDim.x + threadIdx.x;
    if (i < B_SZ * HIDD) g_h0[i] = 0.f;
    if (i == 0) { g_bar_cnt = 0u; *(unsigned*)&g_bar_gen = 0u; }
}

// ---- K1: gates  G[(t*64+b)][j] = emb[X[b,t]] . W_ih[j] + b_ih[j] + b_hh[j] ----
__global__ void __launch_bounds__(256) gates_kernel(const int* __restrict__ X,
                                                    const float* __restrict__ emb,
                                                    const float* __restrict__ W_ih,
                                                    const float* __restrict__ b_ih,
                                                    const float* __restrict__ b_hh) {
    __shared__ float As[16 * 68];
    __shared__ float Bs[16 * 68];
    __shared__ int rowidx[64];
    const int n0 = blockIdx.x * 64;
    const int m0 = blockIdx.y * 64;
    const int tid = threadIdx.x;

    if (tid < 64) {
        int m = m0 + tid;
        int t = m >> 6, b = m & 63;
        rowidx[tid] = X[b * S_LEN + t];
    }
    __syncthreads();

    const int tx = tid & 15, ty = tid >> 4;
    float acc[4][4];
#pragma unroll
    for (int i = 0; i < 4; i++)
#pragma unroll
        for (int j = 0; j < 4; j++) acc[i][j] = 0.f;

    const int lm = tid >> 2;
    const int lk = (tid & 3) * 4;

    for (int k0 = 0; k0 < EMBD; k0 += 16) {
        float4 av = *(const float4*)&emb[(size_t)rowidx[lm] * EMBD + k0 + lk];
        As[(lk + 0) * 68 + lm] = av.x; As[(lk + 1) * 68 + lm] = av.y;
        As[(lk + 2) * 68 + lm] = av.z; As[(lk + 3) * 68 + lm] = av.w;
        float4 bv = *(const float4*)&W_ih[(size_t)(n0 + lm) * EMBD + k0 + lk];
        Bs[(lk + 0) * 68 + lm] = bv.x; Bs[(lk + 1) * 68 + lm] = bv.y;
        Bs[(lk + 2) * 68 + lm] = bv.z; Bs[(lk + 3) * 68 + lm] = bv.w;
        __syncthreads();
#pragma unroll
        for (int kk = 0; kk < 16; kk++) {
            float4 a4 = *(const float4*)&As[kk * 68 + ty * 4];
            float4 b4 = *(const float4*)&Bs[kk * 68 + tx * 4];
            float a[4] = {a4.x, a4.y, a4.z, a4.w};
            float b[4] = {b4.x, b4.y, b4.z, b4.w};
#pragma unroll
            for (int i = 0; i < 4; i++)
#pragma unroll
                for (int j = 0; j < 4; j++) acc[i][j] += a[i] * b[j];
        }
        __syncthreads();
    }
    float4 bi = *(const float4*)&b_ih[n0 + tx * 4];
    float4 bh = *(const float4*)&b_hh[n0 + tx * 4];
    float bias[4] = {bi.x + bh.x, bi.y + bh.y, bi.z + bh.z, bi.w + bh.w};
#pragma unroll
    for (int i = 0; i < 4; i++) {
        int m = m0 + ty * 4 + i;
        float4 o = make_float4(acc[i][0] + bias[0], acc[i][1] + bias[1],
                               acc[i][2] + bias[2], acc[i][3] + bias[3]);
        *(float4*)&g_G[(size_t)m * HIDD + n0 + tx * 4] = o;
    }
}

// ---- K2: persistent recurrence ----
__device__ __forceinline__ void grid_bar(unsigned target) {
    __threadfence();
    __syncthreads();
    if (threadIdx.x == 0) {
        unsigned a = atomicAdd(&g_bar_cnt, 1u);
        if (a == (unsigned)(RNN_NCTA - 1)) {
            atomicExch(&g_bar_cnt, 0u);
            __threadfence();
            atomicAdd((unsigned*)&g_bar_gen, 1u);
        } else {
            while (*(volatile unsigned*)&g_bar_gen < target) __nanosleep(64);
        }
        __threadfence();
    }
    __syncthreads();
}

__global__ void __launch_bounds__(128, 1) rnn_kernel(const float* __restrict__ W_hh) {
    extern __shared__ float smem[];
    float* Wsh = smem;             // [32][260]
    float* hsh = smem + 32 * 260;  // [64][260]
    const int tid = threadIdx.x;
    const int c = blockIdx.x;
    const int jg = c & 31;   // 32 cols each
    const int ks = c >> 5;   // 256 K each

    for (int f = tid * 4; f < 32 * 256; f += 128 * 4) {
        int j = f >> 8, k = f & 255;
        *(float4*)&Wsh[j * 260 + k] =
            *(const float4*)&W_hh[(size_t)(jg * 32 + j) * HIDD + ks * 256 + k];
    }
    __syncthreads();

    const int b0 = (tid >> 3) * 4;
    const int j0 = (tid & 7) * 4;
    unsigned tgt = 0;

    for (int t = 0; t < S_LEN; ++t) {
        const float* hprev = (t == 0) ? g_h0 : (g_OUT + (size_t)(t - 1) * B_SZ * HIDD);
        for (int f = tid * 4; f < 64 * 256; f += 128 * 4) {
            int b = f >> 8, k = f & 255;
            *(float4*)&hsh[b * 260 + k] =
                __ldcg((const float4*)&hprev[(size_t)b * HIDD + ks * 256 + k]);
        }
        __syncthreads();

        float acc[4][4];
#pragma unroll
        for (int i = 0; i < 4; i++)
#pragma unroll
            for (int j = 0; j < 4; j++) acc[i][j] = 0.f;

        for (int kk = 0; kk < 256; kk += 4) {
            float4 hh[4], ww[4];
#pragma unroll
            for (int i = 0; i < 4; i++) hh[i] = *(const float4*)&hsh[(b0 + i) * 260 + kk];
#pragma unroll
            for (int j = 0; j < 4; j++) ww[j] = *(const float4*)&Wsh[(j0 + j) * 260 + kk];
#pragma unroll
            for (int i = 0; i < 4; i++)
#pragma unroll
                for (int j = 0; j < 4; j++) {
                    acc[i][j] += hh[i].x * ww[j].x;
                    acc[i][j] += hh[i].y * ww[j].y;
                    acc[i][j] += hh[i].z * ww[j].z;
                    acc[i][j] += hh[i].w * ww[j].w;
                }
        }
#pragma unroll
        for (int i = 0; i < 4; i++) {
            float4 o = make_float4(acc[i][0], acc[i][1], acc[i][2], acc[i][3]);
            *(float4*)&g_P[ks * (B_SZ * HIDD) + (b0 + i) * HIDD + jg * 32 + j0] = o;
        }
        grid_bar(++tgt);

        {
            int base = c * 512 + tid * 4;
            float4 p0 = __ldcg((const float4*)&g_P[0 * (B_SZ * HIDD) + base]);
            float4 p1 = __ldcg((const float4*)&g_P[1 * (B_SZ * HIDD) + base]);
            float4 p2 = __ldcg((const float4*)&g_P[2 * (B_SZ * HIDD) + base]);
            float4 p3 = __ldcg((const float4*)&g_P[3 * (B_SZ * HIDD) + base]);
            float4 g  = __ldcg((const float4*)&g_G[(size_t)t * B_SZ * HIDD + base]);
            float4 o;
            o.x = tanhf(g.x + p0.x + p1.x + p2.x + p3.x);
            o.y = tanhf(g.y + p0.y + p1.y + p2.y + p3.y);
            o.z = tanhf(g.z + p0.z + p1.z + p2.z + p3.z);
            o.w = tanhf(g.w + p0.w + p1.w + p2.w + p3.w);
            *(float4*)&g_OUT[(size_t)t * B_SZ * HIDD + base] = o;
        }
        grid_bar(++tgt);
    }
}

// ---- K3a: scores[s][b] = <prev[s,b,:], last[b,:]> ----
__global__ void __launch_bounds__(256) scores_kernel() {
    const int s = blockIdx.x;
    const int w = threadIdx.x >> 5, lane = threadIdx.x & 31;
    const float* Pv = g_OUT + (size_t)s * B_SZ * HIDD;
    const float* Lv = g_OUT + (size_t)(S_LEN - 1) * B_SZ * HIDD;
#pragma unroll
    for (int i = 0; i < 8; i++) {
        int b = w * 8 + i;
        const float* p = Pv + (size_t)b * HIDD;
        const float* l = Lv + (size_t)b * HIDD;
        float acc = 0.f;
#pragma unroll 4
        for (int k = lane; k < HIDD; k += 32) acc += p[k] * l[k];
#pragma unroll
        for (int o = 16; o > 0; o >>= 1) acc += __shfl_down_sync(0xffffffffu, acc, o);
        if (lane == 0) g_scores[s * B_SZ + b] = acc;
    }
}

// ---- K3b: softmax over s per b ----
__global__ void __launch_bounds__(512) softmax_kernel() {
    const int b = blockIdx.x;
    const int tid = threadIdx.x;
    __shared__ float red[512];
    float v = (tid < S_LEN - 1) ? g_scores[tid * B_SZ + b] : -1e30f;
    red[tid] = v;
    __syncthreads();
    for (int s = 256; s > 0; s >>= 1) {
        if (tid < s) red[tid] = fmaxf(red[tid], red[tid + s]);
        __syncthreads();
    }
    float m = red[0];
    __syncthreads();
    float e = (tid < S_LEN - 1) ? expf(v - m) : 0.f;
    red[tid] = e;
    __syncthreads();
    for (int s = 256; s > 0; s >>= 1) {
        if (tid < s) red[tid] += red[tid + s];
        __syncthreads();
    }
    float inv = 1.f / red[0];
    if (tid < S_LEN - 1) g_attn[tid * B_SZ + b] = e * inv;
}

// ---- K3c: att_out[b][h] = sum_s attn[s][b] * prev[s][b][h] ----
__global__ void __launch_bounds__(256) attout_kernel() {
    const int b = blockIdx.y;
    const int h = blockIdx.x * 256 + threadIdx.x;
    float acc = 0.f;
#pragma unroll 4
    for (int s = 0; s < S_LEN - 1; s++)
        acc += g_attn[s * B_SZ + b] * g_OUT[(size_t)s * B_SZ * HIDD + (size_t)b * HIDD + h];
    g_attout[b * HIDD + h] = acc;
}

// ---- K4: out[b][n] = [att_out | last] . W_out[n] + b_out[n] ----
__global__ void __launch_bounds__(256) out_gemm_kernel(const float* __restrict__ W_out,
                                                       const float* __restrict__ b_out,
                                                       float* __restrict__ out) {
    __shared__ float Fs[16 * 68];
    __shared__ float Ws[16 * 132];
    const int n0 = blockIdx.x * 128;
    const int tid = threadIdx.x;
    const int tx = tid & 31, ty = tid >> 5;
    const float* last = g_OUT + (size_t)(S_LEN - 1) * B_SZ * HIDD;

    float acc[8][4];
#pragma unroll
    for (int i = 0; i < 8; i++)
#pragma unroll
        for (int j = 0; j < 4; j++) acc[i][j] = 0.f;

    const int mm = tid >> 2;
    const int kq = (tid & 3) * 4;

    for (int k0 = 0; k0 < FEATD; k0 += 16) {
        int k = k0 + kq;
        const float* src = (k < HIDD) ? &g_attout[mm * HIDD + k]
                                      : &last[(size_t)mm * HIDD + (k - HIDD)];
        float4 fv = *(const float4*)src;
        Fs[(kq + 0) * 68 + mm] = fv.x; Fs[(kq + 1) * 68 + mm] = fv.y;
        Fs[(kq + 2) * 68 + mm] = fv.z; Fs[(kq + 3) * 68 + mm] = fv.w;
#pragma unroll
        for (int r = 0; r < 2; r++) {
            int f = tid + r * 256;
            int nn = f >> 2;
            int kq2 = (f & 3) * 4;
            float4 wv = *(const float4*)&W_out[(size_t)(n0 + nn) * FEATD + k0 + kq2];
            Ws[(kq2 + 0) * 132 + nn] = wv.x; Ws[(kq2 + 1) * 132 + nn] = wv.y;
            Ws[(kq2 + 2) * 132 + nn] = wv.z; Ws[(kq2 + 3) * 132 + nn] = wv.w;
        }
        __syncthreads();
#pragma unroll
        for (int kk = 0; kk < 16; kk++) {
            float a[8];
            *(float4*)&a[0] = *(const float4*)&Fs[kk * 68 + ty * 8];
            *(float4*)&a[4] = *(const float4*)&Fs[kk * 68 + ty * 8 + 4];
            float4 w4 = *(const float4*)&Ws[kk * 132 + tx * 4];
            float w[4] = {w4.x, w4.y, w4.z, w4.w};
#pragma unroll
            for (int i = 0; i < 8; i++)
#pragma unroll
                for (int j = 0; j < 4; j++) acc[i][j] += a[i] * w[j];
        }
        __syncthreads();
    }
    float4 bo = *(const float4*)&b_out[n0 + tx * 4];
#pragma unroll
    for (int i = 0; i < 8; i++) {
        int m = ty * 8 + i;
        float4 o = make_float4(acc[i][0] + bo.x, acc[i][1] + bo.y,
                               acc[i][2] + bo.z, acc[i][3] + bo.w);
        *(float4*)&out[(size_t)m * NCLS + n0 + tx * 4] = o;
    }
}

// ---- launch ----
extern "C" void kernel_launch(void* const* d_in, const int* in_sizes, int n_in,
                              void* d_out, int out_size) {
    (void)in_sizes; (void)n_in; (void)out_size;
    const int*   X     = (const int*)d_in[0];
    const float* emb   = (const float*)d_in[1];
    const float* W_ih  = (const float*)d_in[2];
    const float* W_hh  = (const float*)d_in[3];
    const float* b_ih  = (const float*)d_in[4];
    const float* b_hh  = (const float*)d_in[5];
    const float* W_out = (const float*)d_in[6];
    const float* b_out = (const float*)d_in[7];
    float* out = (float*)d_out;

    static bool attr_set = false;
    if (!attr_set) {
        cudaFuncSetAttribute(rnn_kernel, cudaFuncAttributeMaxDynamicSharedMemorySize, RNN_SMEM);
        attr_set = true;
    }

    init_kernel<<<256, 256>>>();
    gates_kernel<<<dim3(HIDD / 64, (S_LEN * B_SZ) / 64), 256>>>(X, emb, W_ih, b_ih, b_hh);
    rnn_kernel<<<RNN_NCTA, 128, RNN_SMEM>>>(W_hh);
    scores_kernel<<<S_LEN - 1, 256>>>();
    softmax_kernel<<<B_SZ, 512>>>();
    attout_kernel<<<dim3(HIDD / 256, B_SZ), 256>>>();
    out_gemm_kernel<<<NCLS / 128, 256>>>(W_out, b_out, out);
}

// round 3
// speedup vs baseline: 1.2860x; 1.2860x over previous
#include <cuda_runtime.h>
#include <cstdint>

#define S_LEN 512
#define B_SZ  64
#define HIDD  1024
#define EMBD  512
#define NCLS  32000
#define FEATD 2048
#define RNN_NCTA 128
// hsh2 (dup, transposed): 256k x 64b x 8B = 128KB ; Wsh_t: 256k x 32j x 4B = 32KB
#define RNN_SMEM (256 * 64 * 8 + 256 * 32 * 4)

// packed f32x2 FMA: d = a*b + d (elementwise on 2 packed floats)
#define FFMA2(d, a, b) asm("fma.rn.f32x2 %0, %1, %2, %0;" : "+l"(d) : "l"(a), "l"(b))

union F2U { unsigned long long u; float2 f; };

// ---- device scratch ----
__device__ float g_G[(size_t)S_LEN * B_SZ * HIDD];
__device__ float g_OUT[(size_t)S_LEN * B_SZ * HIDD];
__device__ float g_P[4 * B_SZ * HIDD];
__device__ float g_h0[B_SZ * HIDD];
__device__ float g_scores[(S_LEN - 1) * B_SZ];
__device__ float g_attn[(S_LEN - 1) * B_SZ];
__device__ float g_attout[B_SZ * HIDD];
__device__ unsigned g_bar_cnt;
__device__ volatile unsigned g_bar_gen;

__global__ void init_kernel() {
    int i = blockIdx.x * blockDim.x + threadIdx.x;
    if (i < B_SZ * HIDD) g_h0[i] = 0.f;
    if (i == 0) { g_bar_cnt = 0u; *(unsigned*)&g_bar_gen = 0u; }
}

// ---- K1: gates  G[(t*64+b)][j] = emb[X[b,t]] . W_ih[j] + b_ih[j] + b_hh[j] ----
// 64x64 tile, 256 threads, micro 4m x 4n, packed f32x2 over n-pairs.
__global__ void __launch_bounds__(256) gates_kernel(const int* __restrict__ X,
                                                    const float* __restrict__ emb,
                                                    const float* __restrict__ W_ih,
                                                    const float* __restrict__ b_ih,
                                                    const float* __restrict__ b_hh) {
    __shared__ float2 As2[16 * 64];   // duplicated (a,a) pairs, [kk][mm]
    __shared__ float  Bs[16 * 68];    // [kk][nn]
    __shared__ int rowidx[64];
    const int n0 = blockIdx.x * 64;
    const int m0 = blockIdx.y * 64;
    const int tid = threadIdx.x;

    if (tid < 64) {
        int m = m0 + tid;
        int t = m >> 6, b = m & 63;
        rowidx[tid] = X[b * S_LEN + t];
    }
    __syncthreads();

    const int tx = tid & 15, ty = tid >> 4;
    unsigned long long acc[4][2];
#pragma unroll
    for (int i = 0; i < 4; i++) { acc[i][0] = 0ull; acc[i][1] = 0ull; }

    const int lm = tid >> 2;
    const int lk = (tid & 3) * 4;

    for (int k0 = 0; k0 < EMBD; k0 += 16) {
        float4 av = *(const float4*)&emb[(size_t)rowidx[lm] * EMBD + k0 + lk];
        As2[(lk + 0) * 64 + lm] = make_float2(av.x, av.x);
        As2[(lk + 1) * 64 + lm] = make_float2(av.y, av.y);
        As2[(lk + 2) * 64 + lm] = make_float2(av.z, av.z);
        As2[(lk + 3) * 64 + lm] = make_float2(av.w, av.w);
        float4 bv = *(const float4*)&W_ih[(size_t)(n0 + lm) * EMBD + k0 + lk];
        Bs[(lk + 0) * 68 + lm] = bv.x; Bs[(lk + 1) * 68 + lm] = bv.y;
        Bs[(lk + 2) * 68 + lm] = bv.z; Bs[(lk + 3) * 68 + lm] = bv.w;
        __syncthreads();
#pragma unroll
        for (int kk = 0; kk < 16; kk++) {
            ulonglong2 a01 = *(const ulonglong2*)&As2[kk * 64 + ty * 4];
            ulonglong2 a23 = *(const ulonglong2*)&As2[kk * 64 + ty * 4 + 2];
            ulonglong2 bp  = *(const ulonglong2*)&Bs[kk * 68 + tx * 4];
            FFMA2(acc[0][0], a01.x, bp.x); FFMA2(acc[0][1], a01.x, bp.y);
            FFMA2(acc[1][0], a01.y, bp.x); FFMA2(acc[1][1], a01.y, bp.y);
            FFMA2(acc[2][0], a23.x, bp.x); FFMA2(acc[2][1], a23.x, bp.y);
            FFMA2(acc[3][0], a23.y, bp.x); FFMA2(acc[3][1], a23.y, bp.y);
        }
        __syncthreads();
    }
    float4 bi = *(const float4*)&b_ih[n0 + tx * 4];
    float4 bh = *(const float4*)&b_hh[n0 + tx * 4];
    float bias[4] = {bi.x + bh.x, bi.y + bh.y, bi.z + bh.z, bi.w + bh.w};
#pragma unroll
    for (int i = 0; i < 4; i++) {
        int m = m0 + ty * 4 + i;
        F2U p0, p1; p0.u = acc[i][0]; p1.u = acc[i][1];
        float4 o = make_float4(p0.f.x + bias[0], p0.f.y + bias[1],
                               p1.f.x + bias[2], p1.f.y + bias[3]);
        *(float4*)&g_G[(size_t)m * HIDD + n0 + tx * 4] = o;
    }
}

// ---- K2: persistent recurrence (128 CTAs x 128 thr), packed f32x2 ----
__device__ __forceinline__ void grid_bar(unsigned target) {
    __threadfence();
    __syncthreads();
    if (threadIdx.x == 0) {
        unsigned a = atomicAdd(&g_bar_cnt, 1u);
        if (a == (unsigned)(RNN_NCTA - 1)) {
            atomicExch(&g_bar_cnt, 0u);
            __threadfence();
            atomicAdd((unsigned*)&g_bar_gen, 1u);
        } else {
            while (*(volatile unsigned*)&g_bar_gen < target) __nanosleep(32);
        }
        __threadfence();
    }
    __syncthreads();
}

__global__ void __launch_bounds__(128, 1) rnn_kernel(const float* __restrict__ W_hh) {
    extern __shared__ char smem_raw[];
    float2* hsh2 = (float2*)smem_raw;                   // [k=256][b=64] dup pairs
    float*  Wsh  = (float*)(smem_raw + 256 * 64 * 8);   // [k=256][j=32]
    const int tid = threadIdx.x;
    const int c = blockIdx.x;
    const int jg = c & 31;   // 32 cols each
    const int ks = c >> 5;   // 256 K each

    // resident W slice, k-major: Wsh[k*32 + j] = W_hh[jg*32+j][ks*256+k]
    {
        int j = tid & 31;
        int kc = (tid >> 5) * 64;     // 4 chunks of 64
        const float* wr = &W_hh[(size_t)(jg * 32 + j) * HIDD + ks * 256 + kc];
#pragma unroll
        for (int q = 0; q < 16; q++) {
            float4 wv = *(const float4*)&wr[q * 4];
            Wsh[(kc + q * 4 + 0) * 32 + j] = wv.x;
            Wsh[(kc + q * 4 + 1) * 32 + j] = wv.y;
            Wsh[(kc + q * 4 + 2) * 32 + j] = wv.z;
            Wsh[(kc + q * 4 + 3) * 32 + j] = wv.w;
        }
    }
    __syncthreads();

    const int b0 = (tid >> 3) * 4;   // 0..60
    const int j0 = (tid & 7) * 4;    // 0..28
    const int sb = tid & 63;         // staging batch
    const int skc = (tid >> 6) * 128; // staging k-chunk (2 halves of 128)
    unsigned tgt = 0;

    for (int t = 0; t < S_LEN; ++t) {
        const float* hprev = (t == 0) ? g_h0 : (g_OUT + (size_t)(t - 1) * B_SZ * HIDD);
        // stage h slice transposed + duplicated: hsh2[k][b] = (h,h)
        {
            const float* hr = &hprev[(size_t)sb * HIDD + ks * 256 + skc];
#pragma unroll
            for (int q = 0; q < 32; q++) {
                float4 hv = __ldcg((const float4*)&hr[q * 4]);
                hsh2[(skc + q * 4 + 0) * 64 + sb] = make_float2(hv.x, hv.x);
                hsh2[(skc + q * 4 + 1) * 64 + sb] = make_float2(hv.y, hv.y);
                hsh2[(skc + q * 4 + 2) * 64 + sb] = make_float2(hv.z, hv.z);
                hsh2[(skc + q * 4 + 3) * 64 + sb] = make_float2(hv.w, hv.w);
            }
        }
        __syncthreads();

        unsigned long long acc[4][2];
#pragma unroll
        for (int i = 0; i < 4; i++) { acc[i][0] = 0ull; acc[i][1] = 0ull; }

#pragma unroll 8
        for (int kk = 0; kk < 256; kk++) {
            ulonglong2 a01 = *(const ulonglong2*)&hsh2[kk * 64 + b0];
            ulonglong2 a23 = *(const ulonglong2*)&hsh2[kk * 64 + b0 + 2];
            ulonglong2 wp  = *(const ulonglong2*)&Wsh[kk * 32 + j0];
            FFMA2(acc[0][0], a01.x, wp.x); FFMA2(acc[0][1], a01.x, wp.y);
            FFMA2(acc[1][0], a01.y, wp.x); FFMA2(acc[1][1], a01.y, wp.y);
            FFMA2(acc[2][0], a23.x, wp.x); FFMA2(acc[2][1], a23.x, wp.y);
            FFMA2(acc[3][0], a23.y, wp.x); FFMA2(acc[3][1], a23.y, wp.y);
        }
#pragma unroll
        for (int i = 0; i < 4; i++) {
            F2U p0, p1; p0.u = acc[i][0]; p1.u = acc[i][1];
            float4 o = make_float4(p0.f.x, p0.f.y, p1.f.x, p1.f.y);
            *(float4*)&g_P[ks * (B_SZ * HIDD) + (b0 + i) * HIDD + jg * 32 + j0] = o;
        }
        grid_bar(++tgt);

        {
            int base = c * 512 + tid * 4;
            float4 p0 = __ldcg((const float4*)&g_P[0 * (B_SZ * HIDD) + base]);
            float4 p1 = __ldcg((const float4*)&g_P[1 * (B_SZ * HIDD) + base]);
            float4 p2 = __ldcg((const float4*)&g_P[2 * (B_SZ * HIDD) + base]);
            float4 p3 = __ldcg((const float4*)&g_P[3 * (B_SZ * HIDD) + base]);
            float4 g  = __ldcg((const float4*)&g_G[(size_t)t * B_SZ * HIDD + base]);
            float4 o;
            o.x = tanhf(g.x + p0.x + p1.x + p2.x + p3.x);
            o.y = tanhf(g.y + p0.y + p1.y + p2.y + p3.y);
            o.z = tanhf(g.z + p0.z + p1.z + p2.z + p3.z);
            o.w = tanhf(g.w + p0.w + p1.w + p2.w + p3.w);
            *(float4*)&g_OUT[(size_t)t * B_SZ * HIDD + base] = o;
        }
        grid_bar(++tgt);
    }
}

// ---- K3a: scores ----
__global__ void __launch_bounds__(256) scores_kernel() {
    const int s = blockIdx.x;
    const int w = threadIdx.x >> 5, lane = threadIdx.x & 31;
    const float* Pv = g_OUT + (size_t)s * B_SZ * HIDD;
    const float* Lv = g_OUT + (size_t)(S_LEN - 1) * B_SZ * HIDD;
#pragma unroll
    for (int i = 0; i < 8; i++) {
        int b = w * 8 + i;
        const float* p = Pv + (size_t)b * HIDD;
        const float* l = Lv + (size_t)b * HIDD;
        float acc = 0.f;
#pragma unroll 4
        for (int k = lane; k < HIDD; k += 32) acc += p[k] * l[k];
#pragma unroll
        for (int o = 16; o > 0; o >>= 1) acc += __shfl_down_sync(0xffffffffu, acc, o);
        if (lane == 0) g_scores[s * B_SZ + b] = acc;
    }
}

// ---- K3b: softmax over s per b ----
__global__ void __launch_bounds__(512) softmax_kernel() {
    const int b = blockIdx.x;
    const int tid = threadIdx.x;
    __shared__ float red[512];
    float v = (tid < S_LEN - 1) ? g_scores[tid * B_SZ + b] : -1e30f;
    red[tid] = v;
    __syncthreads();
    for (int s = 256; s > 0; s >>= 1) {
        if (tid < s) red[tid] = fmaxf(red[tid], red[tid + s]);
        __syncthreads();
    }
    float m = red[0];
    __syncthreads();
    float e = (tid < S_LEN - 1) ? expf(v - m) : 0.f;
    red[tid] = e;
    __syncthreads();
    for (int s = 256; s > 0; s >>= 1) {
        if (tid < s) red[tid] += red[tid + s];
        __syncthreads();
    }
    float inv = 1.f / red[0];
    if (tid < S_LEN - 1) g_attn[tid * B_SZ + b] = e * inv;
}

// ---- K3c: att_out ----
__global__ void __launch_bounds__(256) attout_kernel() {
    const int b = blockIdx.y;
    const int h = blockIdx.x * 256 + threadIdx.x;
    float acc = 0.f;
#pragma unroll 4
    for (int s = 0; s < S_LEN - 1; s++)
        acc += g_attn[s * B_SZ + b] * g_OUT[(size_t)s * B_SZ * HIDD + (size_t)b * HIDD + h];
    g_attout[b * HIDD + h] = acc;
}

// ---- K4: out[b][n] = [att_out | last] . W_out[n] + b_out[n], packed f32x2 ----
__global__ void __launch_bounds__(256) out_gemm_kernel(const float* __restrict__ W_out,
                                                       const float* __restrict__ b_out,
                                                       float* __restrict__ out) {
    __shared__ float2 Fs2[16 * 64];   // duplicated feature pairs [kk][mm]
    __shared__ float  Ws[16 * 132];   // [kk][nn]
    const int n0 = blockIdx.x * 128;
    const int tid = threadIdx.x;
    const int tx = tid & 31, ty = tid >> 5;
    const float* last = g_OUT + (size_t)(S_LEN - 1) * B_SZ * HIDD;

    unsigned long long acc[8][2];
#pragma unroll
    for (int i = 0; i < 8; i++) { acc[i][0] = 0ull; acc[i][1] = 0ull; }

    const int mm = tid >> 2;
    const int kq = (tid & 3) * 4;

    for (int k0 = 0; k0 < FEATD; k0 += 16) {
        int k = k0 + kq;
        const float* src = (k < HIDD) ? &g_attout[mm * HIDD + k]
                                      : &last[(size_t)mm * HIDD + (k - HIDD)];
        float4 fv = *(const float4*)src;
        Fs2[(kq + 0) * 64 + mm] = make_float2(fv.x, fv.x);
        Fs2[(kq + 1) * 64 + mm] = make_float2(fv.y, fv.y);
        Fs2[(kq + 2) * 64 + mm] = make_float2(fv.z, fv.z);
        Fs2[(kq + 3) * 64 + mm] = make_float2(fv.w, fv.w);
#pragma unroll
        for (int r = 0; r < 2; r++) {
            int f = tid + r * 256;
            int nn = f >> 2;
            int kq2 = (f & 3) * 4;
            float4 wv = *(const float4*)&W_out[(size_t)(n0 + nn) * FEATD + k0 + kq2];
            Ws[(kq2 + 0) * 132 + nn] = wv.x; Ws[(kq2 + 1) * 132 + nn] = wv.y;
            Ws[(kq2 + 2) * 132 + nn] = wv.z; Ws[(kq2 + 3) * 132 + nn] = wv.w;
        }
        __syncthreads();
#pragma unroll
        for (int kk = 0; kk < 16; kk++) {
            ulonglong2 a01 = *(const ulonglong2*)&Fs2[kk * 64 + ty * 8];
            ulonglong2 a23 = *(const ulonglong2*)&Fs2[kk * 64 + ty * 8 + 2];
            ulonglong2 a45 = *(const ulonglong2*)&Fs2[kk * 64 + ty * 8 + 4];
            ulonglong2 a67 = *(const ulonglong2*)&Fs2[kk * 64 + ty * 8 + 6];
            ulonglong2 wp  = *(const ulonglong2*)&Ws[kk * 132 + tx * 4];
            FFMA2(acc[0][0], a01.x, wp.x); FFMA2(acc[0][1], a01.x, wp.y);
            FFMA2(acc[1][0], a01.y, wp.x); FFMA2(acc[1][1], a01.y, wp.y);
            FFMA2(acc[2][0], a23.x, wp.x); FFMA2(acc[2][1], a23.x, wp.y);
            FFMA2(acc[3][0], a23.y, wp.x); FFMA2(acc[3][1], a23.y, wp.y);
            FFMA2(acc[4][0], a45.x, wp.x); FFMA2(acc[4][1], a45.x, wp.y);
            FFMA2(acc[5][0], a45.y, wp.x); FFMA2(acc[5][1], a45.y, wp.y);
            FFMA2(acc[6][0], a67.x, wp.x); FFMA2(acc[6][1], a67.x, wp.y);
            FFMA2(acc[7][0], a67.y, wp.x); FFMA2(acc[7][1], a67.y, wp.y);
        }
        __syncthreads();
    }
    float4 bo = *(const float4*)&b_out[n0 + tx * 4];
#pragma unroll
    for (int i = 0; i < 8; i++) {
        int m = ty * 8 + i;
        F2U p0, p1; p0.u = acc[i][0]; p1.u = acc[i][1];
        float4 o = make_float4(p0.f.x + bo.x, p0.f.y + bo.y,
                               p1.f.x + bo.z, p1.f.y + bo.w);
        *(float4*)&out[(size_t)m * NCLS + n0 + tx * 4] = o;
    }
}

// ---- launch ----
extern "C" void kernel_launch(void* const* d_in, const int* in_sizes, int n_in,
                              void* d_out, int out_size) {
    (void)in_sizes; (void)n_in; (void)out_size;
    const int*   X     = (const int*)d_in[0];
    const float* emb   = (const float*)d_in[1];
    const float* W_ih  = (const float*)d_in[2];
    const float* W_hh  = (const float*)d_in[3];
    const float* b_ih  = (const float*)d_in[4];
    const float* b_hh  = (const float*)d_in[5];
    const float* W_out = (const float*)d_in[6];
    const float* b_out = (const float*)d_in[7];
    float* out = (float*)d_out;

    static bool attr_set = false;
    if (!attr_set) {
        cudaFuncSetAttribute(rnn_kernel, cudaFuncAttributeMaxDynamicSharedMemorySize, RNN_SMEM);
        attr_set = true;
    }

    init_kernel<<<256, 256>>>();
    gates_kernel<<<dim3(HIDD / 64, (S_LEN * B_SZ) / 64), 256>>>(X, emb, W_ih, b_ih, b_hh);
    rnn_kernel<<<RNN_NCTA, 128, RNN_SMEM>>>(W_hh);
    scores_kernel<<<S_LEN - 1, 256>>>();
    softmax_kernel<<<B_SZ, 512>>>();
    attout_kernel<<<dim3(HIDD / 256, B_SZ), 256>>>();
    out_gemm_kernel<<<NCLS / 128, 256>>>(W_out, b_out, out);
}